// round 11
// baseline (speedup 1.0000x reference)
#include <cuda_runtime.h>
#include <cuda_bf16.h>
#include <cuda_fp16.h>
#include <cstdint>

#define L 4096
#define CC 256
#define NB 2
#define NH 4
#define HD 64

// ---------------- mma / ldmatrix / cp.async helpers -------------------------
__device__ __forceinline__ void mma_bf16(float* d,
                                         uint32_t a0, uint32_t a1, uint32_t a2, uint32_t a3,
                                         uint32_t b0, uint32_t b1) {
    asm volatile(
        "mma.sync.aligned.m16n8k16.row.col.f32.bf16.bf16.f32 "
        "{%0,%1,%2,%3}, {%4,%5,%6,%7}, {%8,%9}, {%0,%1,%2,%3};"
        : "+f"(d[0]), "+f"(d[1]), "+f"(d[2]), "+f"(d[3])
        : "r"(a0), "r"(a1), "r"(a2), "r"(a3), "r"(b0), "r"(b1));
}
__device__ __forceinline__ void mma_f16(float* d,
                                        uint32_t a0, uint32_t a1, uint32_t a2, uint32_t a3,
                                        uint32_t b0, uint32_t b1) {
    asm volatile(
        "mma.sync.aligned.m16n8k16.row.col.f32.f16.f16.f32 "
        "{%0,%1,%2,%3}, {%4,%5,%6,%7}, {%8,%9}, {%0,%1,%2,%3};"
        : "+f"(d[0]), "+f"(d[1]), "+f"(d[2]), "+f"(d[3])
        : "r"(a0), "r"(a1), "r"(a2), "r"(a3), "r"(b0), "r"(b1));
}
__device__ __forceinline__ uint32_t pkbf(float lo, float hi) {
    __nv_bfloat162 h = __floats2bfloat162_rn(lo, hi);
    return *(uint32_t*)&h;
}
__device__ __forceinline__ uint32_t pkhf(float lo, float hi) {
    __half2 h = __floats2half2_rn(lo, hi);
    return *(uint32_t*)&h;
}
__device__ __forceinline__ uint32_t ex2pk(float lo, float hi) {
    uint32_t h, r;
    asm("cvt.rn.f16x2.f32 %0, %1, %2;" : "=r"(h) : "f"(hi), "f"(lo));
    asm("ex2.approx.f16x2 %0, %1;" : "=r"(r) : "r"(h));
    return r;
}
__device__ __forceinline__ uint32_t hadd2u(uint32_t a, uint32_t b) {
    uint32_t d;
    asm("add.f16x2 %0, %1, %2;" : "=r"(d) : "r"(a), "r"(b));
    return d;
}
__device__ __forceinline__ float h2sum(uint32_t v) {
    __half2 h = *(__half2*)&v;
    float2 f = __half22float2(h);
    return f.x + f.y;
}
__device__ __forceinline__ uint32_t smem_u32(const void* p) {
    return (uint32_t)__cvta_generic_to_shared(p);
}
__device__ __forceinline__ void ldm_x4(uint32_t* r, uint32_t a) {
    asm volatile("ldmatrix.sync.aligned.m8n8.x4.shared.b16 {%0,%1,%2,%3}, [%4];"
        : "=r"(r[0]), "=r"(r[1]), "=r"(r[2]), "=r"(r[3]) : "r"(a));
}
__device__ __forceinline__ void ldm_x4t(uint32_t* r, uint32_t a) {
    asm volatile("ldmatrix.sync.aligned.m8n8.x4.trans.shared.b16 {%0,%1,%2,%3}, [%4];"
        : "=r"(r[0]), "=r"(r[1]), "=r"(r[2]), "=r"(r[3]) : "r"(a));
}
#define CPA16(dst, src) \
    asm volatile("cp.async.cg.shared.global [%0], [%1], 16;" :: "r"(dst), "l"(src) : "memory")
#define CPA_COMMIT() asm volatile("cp.async.commit_group;" ::: "memory")
#define CPA_WAIT1()  asm volatile("cp.async.wait_group 1;" ::: "memory")
#define CPA_WAIT0()  asm volatile("cp.async.wait_group 0;" ::: "memory")

// ---------------- scratch ----------------------------------------------------
__device__ __nv_bfloat16 g_qt[(size_t)NB * NH * L * HD];   // [nh][i][d] (pre-scaled log2e/8)
__device__ __nv_bfloat16 g_kt[(size_t)NB * NH * L * HD];   // [nh][j][d]
__device__ __half        g_vt[(size_t)NB * CC * L];        // [nb][ch][j]  fp16
__device__ __nv_bfloat16 g_xnb[(size_t)NB * CC * L];
__device__ __nv_bfloat16 g_ob[(size_t)NB * CC * L];
__device__ __nv_bfloat16 g_wq[CC * CC], g_wk[CC * CC], g_wv[CC * CC], g_wp[CC * CC];
__device__ float         g_part[16 * 8 * 2];

#define QSCALE 0.18033688011112042f   // 0.125 * log2(e)

// ---------------- prep: wcvt + gn_part + mask fused --------------------------
// blocks [0,128): gn partials ; [128,384): weight cvt ; [384,416): mask cast
__global__ void prep_kernel(const float* __restrict__ x,
                            const float* __restrict__ qw, const float* __restrict__ kw,
                            const float* __restrict__ vw, const float* __restrict__ pw,
                            const int* __restrict__ mask,
                            float* __restrict__ part,
                            __nv_bfloat16* __restrict__ wq, __nv_bfloat16* __restrict__ wk,
                            __nv_bfloat16* __restrict__ wv, __nv_bfloat16* __restrict__ wp,
                            float* __restrict__ mout) {
    int b = blockIdx.x;
    if (b < 128) {
        int ng = b >> 3, sl = b & 7;
        const float4* xp = (const float4*)(x + ((size_t)ng * 32) * L + (size_t)sl * 16384);
        float s = 0.f, s2 = 0.f;
        for (int i = threadIdx.x; i < 4096; i += 256) {
            float4 v = xp[i];
            s += v.x + v.y + v.z + v.w;
            s2 += v.x * v.x + v.y * v.y + v.z * v.z + v.w * v.w;
        }
        __shared__ float sh1[256], sh2[256];
        sh1[threadIdx.x] = s; sh2[threadIdx.x] = s2;
        __syncthreads();
        for (int st = 128; st > 0; st >>= 1) {
            if (threadIdx.x < st) {
                sh1[threadIdx.x] += sh1[threadIdx.x + st];
                sh2[threadIdx.x] += sh2[threadIdx.x + st];
            }
            __syncthreads();
        }
        if (threadIdx.x == 0) {
            part[(ng * 8 + sl) * 2 + 0] = sh1[0];
            part[(ng * 8 + sl) * 2 + 1] = sh2[0];
        }
    } else if (b < 384) {
        int i = (b - 128) * 256 + threadIdx.x;
        wq[i] = __float2bfloat16(qw[i] * QSCALE);
        wk[i] = __float2bfloat16(kw[i]);
        wv[i] = __float2bfloat16(vw[i]);
        wp[i] = __float2bfloat16(pw[i]);
    } else {
        int i = (b - 384) * 256 + threadIdx.x;
        if (i < NB * L) mout[i] = (float)mask[i];
    }
}

__global__ void gn_apply_kernel(const float* __restrict__ x,
                                const float* __restrict__ part,
                                const float* __restrict__ w,
                                const float* __restrict__ b,
                                __nv_bfloat16* __restrict__ xnb) {
    size_t base = (size_t)blockIdx.x * 8192;
    int ng = (int)(base >> 17);
    float s = 0.f, s2 = 0.f;
#pragma unroll
    for (int sl = 0; sl < 8; sl++) {
        s  += part[(ng * 8 + sl) * 2 + 0];
        s2 += part[(ng * 8 + sl) * 2 + 1];
    }
    float mean = s / 131072.f;
    float var = s2 / 131072.f - mean * mean;
    float rstd = rsqrtf(var + 1e-5f);
    const float4* xp = (const float4*)(x + base);
    for (int i = threadIdx.x; i < 2048; i += 256) {
        size_t idx = base + (size_t)i * 4;
        int c = (int)((idx >> 12) & 255);
        float sc = rstd * w[c], of = b[c] - mean * sc;
        float4 v = xp[i];
        __nv_bfloat162 lo = __floats2bfloat162_rn(v.x * sc + of, v.y * sc + of);
        __nv_bfloat162 hi = __floats2bfloat162_rn(v.z * sc + of, v.w * sc + of);
        uint2 pk = make_uint2(*(uint32_t*)&lo, *(uint32_t*)&hi);
        *(uint2*)&xnb[idx] = pk;
    }
}

// ---------------- conv core: 64m x 128n tile, k=256, triple-buffered --------
#define CONV_SMEM 41472
__device__ __forceinline__ __nv_bfloat16 (*WsB(char* csm, int buf))[40] {
    return (__nv_bfloat16(*)[40])(csm + buf * 5120);
}
__device__ __forceinline__ __nv_bfloat16 (*XsB(char* csm, int buf))[136] {
    return (__nv_bfloat16(*)[136])(csm + 15360 + buf * 8704);
}

__device__ __forceinline__
void conv_stage(char* csm, int buf, const __nv_bfloat16* W, const __nv_bfloat16* X,
                int m0, int n0, int k0, int t) {
    {
        int row = t >> 2, seg = t & 3;
        CPA16(smem_u32(&WsB(csm, buf)[row][seg * 8]),
              W + (size_t)(m0 + row) * CC + k0 + seg * 8);
    }
#pragma unroll
    for (int rep = 0; rep < 2; rep++) {
        int idx = t + rep * 256;
        int row = idx >> 4, seg = idx & 15;
        CPA16(smem_u32(&XsB(csm, buf)[row][seg * 8]),
              X + (size_t)(k0 + row) * L + n0 + seg * 8);
    }
    CPA_COMMIT();
}

// warp layout: 4 m-warps x 2 n-warps; per-warp 16m x 64n
__device__ __forceinline__
void conv_core(char* csm, const __nv_bfloat16* W, const __nv_bfloat16* X,
               int m0, int n0, float acc[8][4]) {
    const int t = threadIdx.x, lane = t & 31, w = t >> 5;
    const int mw = (w >> 1) * 16, nb0 = (w & 1) * 64;
    const int l16 = lane & 15, lh = lane >> 4;
    conv_stage(csm, 0, W, X, m0, n0, 0, t);
    conv_stage(csm, 1, W, X, m0, n0, 32, t);
    for (int i = 0; i < 8; i++) {
        if (i < 7) CPA_WAIT1(); else CPA_WAIT0();
        __syncthreads();
        if (i + 2 < 8) conv_stage(csm, (i + 2) % 3, W, X, m0, n0, (i + 2) * 32, t);
        __nv_bfloat16 (*Ws)[40]  = WsB(csm, i % 3);
        __nv_bfloat16 (*Xs)[136] = XsB(csm, i % 3);
#pragma unroll
        for (int kd = 0; kd < 2; kd++) {
            uint32_t a[4];
            ldm_x4(a, smem_u32(&Ws[mw + l16][kd * 16 + lh * 8]));
#pragma unroll
            for (int nbp = 0; nbp < 4; nbp++) {
                uint32_t b[4];
                ldm_x4t(b, smem_u32(&Xs[kd * 16 + l16][nb0 + nbp * 16 + lh * 8]));
                mma_bf16(acc[2 * nbp],     a[0], a[1], a[2], a[3], b[0], b[1]);
                mma_bf16(acc[2 * nbp + 1], a[0], a[1], a[2], a[3], b[2], b[3]);
            }
        }
    }
}

// fused q/k/v conv: z = type*2 + batch ; m-tiles of 64 = one head block
__global__ __launch_bounds__(256, 3)
void qkv_kernel(const __nv_bfloat16* __restrict__ xnb,
                const __nv_bfloat16* __restrict__ wq, const __nv_bfloat16* __restrict__ wk,
                const __nv_bfloat16* __restrict__ wv,
                const float* __restrict__ qbias, const float* __restrict__ kbias,
                const float* __restrict__ vbias,
                __nv_bfloat16* __restrict__ qt, __nv_bfloat16* __restrict__ kt,
                __half* __restrict__ vt) {
    __shared__ __align__(16) char csm[CONV_SMEM];
    const int type = blockIdx.z >> 1, nbatch = blockIdx.z & 1;
    const __nv_bfloat16* W = type == 0 ? wq : type == 1 ? wk : wv;
    const float* Bias = type == 0 ? qbias : type == 1 ? kbias : vbias;
    const float osc = type == 0 ? QSCALE : 1.0f;
    const __nv_bfloat16* X = xnb + (size_t)nbatch * CC * L;
    const int n0 = blockIdx.x * 128, m0 = blockIdx.y * 64;
    const int t = threadIdx.x, lane = t & 31, w = t >> 5;
    const int g = lane >> 2, t4 = lane & 3;
    const int mw = (w >> 1) * 16, nb0 = (w & 1) * 64;

    float acc[8][4];
#pragma unroll
    for (int a = 0; a < 8; a++)
#pragma unroll
        for (int p = 0; p < 4; p++) acc[a][p] = 0.f;
    conv_core(csm, W, X, m0, n0, acc);

    float b0v = Bias[m0 + mw + g] * osc, b1v = Bias[m0 + mw + g + 8] * osc;
    if (type < 2) {
        // transpose epilogue into [nh][pos][d]; head = blockIdx.y
        __syncthreads();
        __nv_bfloat16 (*T)[72] = (__nv_bfloat16(*)[72])csm;   // [128 n][64 d]
#pragma unroll
        for (int f = 0; f < 8; f++) {
            int n = nb0 + 16 * (f >> 1) + 8 * (f & 1) + 2 * t4;
            T[n][mw + g]         = __float2bfloat16(acc[f][0] + b0v);
            T[n + 1][mw + g]     = __float2bfloat16(acc[f][1] + b0v);
            T[n][mw + g + 8]     = __float2bfloat16(acc[f][2] + b1v);
            T[n + 1][mw + g + 8] = __float2bfloat16(acc[f][3] + b1v);
        }
        __syncthreads();
        __nv_bfloat16* Out = (type == 0 ? qt : kt) +
            ((size_t)(nbatch * 4 + blockIdx.y) * L + n0) * HD;
        for (int u = t; u < 4096; u += 256) {
            int n = u >> 5, dp = u & 31;
            *(uint32_t*)(Out + (size_t)n * HD + 2 * dp) = *(uint32_t*)&T[n][2 * dp];
        }
    } else {
        int mA = m0 + mw + g, mB = mA + 8;
#pragma unroll
        for (int f = 0; f < 8; f++) {
            int n = n0 + nb0 + 16 * (f >> 1) + 8 * (f & 1) + 2 * t4;
            *(uint32_t*)&vt[((size_t)nbatch * CC + mA) * L + n] = pkhf(acc[f][0] + b0v, acc[f][1] + b0v);
            *(uint32_t*)&vt[((size_t)nbatch * CC + mB) * L + n] = pkhf(acc[f][2] + b1v, acc[f][3] + b1v);
        }
    }
}

// proj conv -> fp32 + residual
__global__ __launch_bounds__(256, 3)
void proj_kernel(const __nv_bfloat16* __restrict__ ob, const __nv_bfloat16* __restrict__ wp,
                 const float* __restrict__ pbias, const float* __restrict__ x,
                 float* __restrict__ out) {
    __shared__ __align__(16) char csm[CONV_SMEM];
    const int nbatch = blockIdx.z;
    const size_t off = (size_t)nbatch * CC * L;
    const int n0 = blockIdx.x * 128, m0 = blockIdx.y * 64;
    const int t = threadIdx.x, lane = t & 31, w = t >> 5;
    const int g = lane >> 2, t4 = lane & 3;
    const int mw = (w >> 1) * 16, nb0 = (w & 1) * 64;

    float acc[8][4];
#pragma unroll
    for (int a = 0; a < 8; a++)
#pragma unroll
        for (int p = 0; p < 4; p++) acc[a][p] = 0.f;
    conv_core(csm, wp, ob + off, m0, n0, acc);

    float b0v = pbias[m0 + mw + g], b1v = pbias[m0 + mw + g + 8];
    int mA = m0 + mw + g, mB = mA + 8;
#pragma unroll
    for (int f = 0; f < 8; f++) {
        int n = n0 + nb0 + 16 * (f >> 1) + 8 * (f & 1) + 2 * t4;
        float2 rA = *(const float2*)&x[off + (size_t)mA * L + n];
        float2 rB = *(const float2*)&x[off + (size_t)mB * L + n];
        *(float2*)&out[off + (size_t)mA * L + n] =
            make_float2(acc[f][0] + b0v + rA.x, acc[f][1] + b0v + rA.y);
        *(float2*)&out[off + (size_t)mB * L + n] =
            make_float2(acc[f][2] + b1v + rB.x, acc[f][3] + b1v + rB.y);
    }
}

// ---------------- flash attention: 128-thr CTAs, 2 CTAs/SM ------------------
// 4 warps x 32 i-rows = i-tile 128; j-tile 64; triple-buffered K/V.
// Row sums via HADD2 of the exact f16 P fragments (fma pipe) - no ones-mma.
#define FLASH_SMEM 55296
__global__ __launch_bounds__(128, 2)
void flash_kernel(const __nv_bfloat16* __restrict__ qt,
                  const __nv_bfloat16* __restrict__ kt,
                  const __half* __restrict__ vt,
                  __nv_bfloat16* __restrict__ o) {
    extern __shared__ __align__(16) char fsm[];
    const int t = threadIdx.x, lane = t & 31, w = t >> 5;   // w in 0..3
    const int g = lane >> 2, t4 = lane & 3;
    const int lrow = (lane & 7) + ((lane >> 4) << 3);
    const int lcol = ((lane >> 3) & 1) * 8;
    const int nh = blockIdx.y;
    const int nb = nh >> 2, h = nh & 3;
    const int i0 = blockIdx.x * 128, iw = i0 + w * 32;

    // two A-fragment sets: rows iw..iw+15 and iw+16..iw+31
    const __nv_bfloat16* Qb0 = qt + ((size_t)nh * L + iw) * HD;
    const __nv_bfloat16* Qb1 = Qb0 + (size_t)16 * HD;
    uint32_t qa0[4][4], qa1[4][4];
#pragma unroll
    for (int kd = 0; kd < 4; kd++) {
        qa0[kd][0] = *(const uint32_t*)(Qb0 + (size_t)g * HD + 16 * kd + 2 * t4);
        qa0[kd][1] = *(const uint32_t*)(Qb0 + (size_t)(g + 8) * HD + 16 * kd + 2 * t4);
        qa0[kd][2] = *(const uint32_t*)(Qb0 + (size_t)g * HD + 16 * kd + 8 + 2 * t4);
        qa0[kd][3] = *(const uint32_t*)(Qb0 + (size_t)(g + 8) * HD + 16 * kd + 8 + 2 * t4);
        qa1[kd][0] = *(const uint32_t*)(Qb1 + (size_t)g * HD + 16 * kd + 2 * t4);
        qa1[kd][1] = *(const uint32_t*)(Qb1 + (size_t)(g + 8) * HD + 16 * kd + 2 * t4);
        qa1[kd][2] = *(const uint32_t*)(Qb1 + (size_t)g * HD + 16 * kd + 8 + 2 * t4);
        qa1[kd][3] = *(const uint32_t*)(Qb1 + (size_t)(g + 8) * HD + 16 * kd + 8 + 2 * t4);
    }

    float O0[8][4], O1[8][4];
#pragma unroll
    for (int a = 0; a < 8; a++)
#pragma unroll
        for (int p = 0; p < 4; p++) { O0[a][p] = 0.f; O1[a][p] = 0.f; }
    // f32 row-sum accumulators: rows g, g+8, g+16, g+24 (cols owned by this lane)
    float lr0 = 0.f, lr8 = 0.f, lr16 = 0.f, lr24 = 0.f;

    const __nv_bfloat16* Kg = kt + (size_t)nh * L * HD;
    const __half* Vg = vt + (size_t)(nb * CC + h * HD) * L;

    auto stage = [&](int buf, int j0) {
        __nv_bfloat16 (*Kt_)[72] = (__nv_bfloat16(*)[72])(fsm + buf * 9216);
        __half (*Vs_)[72] = (__half(*)[72])(fsm + 27648 + buf * 9216);
#pragma unroll
        for (int rep = 0; rep < 4; rep++) {
            int idx = t + rep * 128;
            int r = idx >> 3, seg = idx & 7;
            CPA16(smem_u32(&Kt_[r][seg * 8]), Kg + (size_t)(j0 + r) * HD + seg * 8);
            CPA16(smem_u32(&Vs_[r][seg * 8]), Vg + (size_t)r * L + j0 + seg * 8);
        }
        CPA_COMMIT();
    };

    stage(0, 0);
    stage(1, 64);
    __syncthreads();

    for (int jt = 0; jt < 64; jt++) {
        if (jt < 63) CPA_WAIT1(); else CPA_WAIT0();
        __syncthreads();
        if (jt < 62) stage((jt + 2) % 3, (jt + 2) * 64);
        __nv_bfloat16 (*Kt_)[72] = (__nv_bfloat16(*)[72])(fsm + (jt % 3) * 9216);
        __half (*Vs_)[72] = (__half(*)[72])(fsm + 27648 + (jt % 3) * 9216);

        // S = Q K^T for both row-sets; each B-frag feeds 4 mmas
        float S0[8][4], S1[8][4];
#pragma unroll
        for (int a = 0; a < 8; a++)
#pragma unroll
            for (int p = 0; p < 4; p++) { S0[a][p] = 0.f; S1[a][p] = 0.f; }
#pragma unroll
        for (int kd = 0; kd < 4; kd++) {
#pragma unroll
            for (int sbp = 0; sbp < 4; sbp++) {
                uint32_t b[4];
                ldm_x4(b, smem_u32(&Kt_[16 * sbp + lrow][16 * kd + lcol]));
                mma_bf16(S0[2 * sbp],     qa0[kd][0], qa0[kd][1], qa0[kd][2], qa0[kd][3], b[0], b[1]);
                mma_bf16(S0[2 * sbp + 1], qa0[kd][0], qa0[kd][1], qa0[kd][2], qa0[kd][3], b[2], b[3]);
                mma_bf16(S1[2 * sbp],     qa1[kd][0], qa1[kd][1], qa1[kd][2], qa1[kd][3], b[0], b[1]);
                mma_bf16(S1[2 * sbp + 1], qa1[kd][0], qa1[kd][1], qa1[kd][2], qa1[kd][3], b[2], b[3]);
            }
        }

        // exp2 -> f16 P frags; O += P V^T ; row sums via HADD2 (fma pipe)
        uint32_t h0 = 0, h8 = 0, h16 = 0, h24 = 0;   // f16x2 per-tile partials
#pragma unroll
        for (int kk = 0; kk < 4; kk++) {
            uint32_t pa0 = ex2pk(S0[2 * kk][0],     S0[2 * kk][1]);
            uint32_t pa1 = ex2pk(S0[2 * kk][2],     S0[2 * kk][3]);
            uint32_t pa2 = ex2pk(S0[2 * kk + 1][0], S0[2 * kk + 1][1]);
            uint32_t pa3 = ex2pk(S0[2 * kk + 1][2], S0[2 * kk + 1][3]);
            uint32_t pb0 = ex2pk(S1[2 * kk][0],     S1[2 * kk][1]);
            uint32_t pb1 = ex2pk(S1[2 * kk][2],     S1[2 * kk][3]);
            uint32_t pb2 = ex2pk(S1[2 * kk + 1][0], S1[2 * kk + 1][1]);
            uint32_t pb3 = ex2pk(S1[2 * kk + 1][2], S1[2 * kk + 1][3]);
            h0  = hadd2u(h0,  hadd2u(pa0, pa2));
            h8  = hadd2u(h8,  hadd2u(pa1, pa3));
            h16 = hadd2u(h16, hadd2u(pb0, pb2));
            h24 = hadd2u(h24, hadd2u(pb1, pb3));
#pragma unroll
            for (int cbp = 0; cbp < 4; cbp++) {
                uint32_t b[4];
                ldm_x4(b, smem_u32(&Vs_[16 * cbp + lrow][16 * kk + lcol]));
                mma_f16(O0[2 * cbp],     pa0, pa1, pa2, pa3, b[0], b[1]);
                mma_f16(O0[2 * cbp + 1], pa0, pa1, pa2, pa3, b[2], b[3]);
                mma_f16(O1[2 * cbp],     pb0, pb1, pb2, pb3, b[0], b[1]);
                mma_f16(O1[2 * cbp + 1], pb0, pb1, pb2, pb3, b[2], b[3]);
            }
        }
        lr0  += h2sum(h0);
        lr8  += h2sum(h8);
        lr16 += h2sum(h16);
        lr24 += h2sum(h24);
    }

    // complete row sums across the lane quad (t4 dimension = columns)
    lr0  += __shfl_xor_sync(0xffffffffu, lr0, 1);
    lr0  += __shfl_xor_sync(0xffffffffu, lr0, 2);
    lr8  += __shfl_xor_sync(0xffffffffu, lr8, 1);
    lr8  += __shfl_xor_sync(0xffffffffu, lr8, 2);
    lr16 += __shfl_xor_sync(0xffffffffu, lr16, 1);
    lr16 += __shfl_xor_sync(0xffffffffu, lr16, 2);
    lr24 += __shfl_xor_sync(0xffffffffu, lr24, 1);
    lr24 += __shfl_xor_sync(0xffffffffu, lr24, 2);
    float i00 = 1.f / lr0, i01 = 1.f / lr8, i10 = 1.f / lr16, i11 = 1.f / lr24;

    __syncthreads();
    __nv_bfloat16 (*OT)[72] = (__nv_bfloat16(*)[72])fsm;   // [128 i][64 c]
#pragma unroll
    for (int cb = 0; cb < 8; cb++) {
        int c = 8 * cb + 2 * t4;
        *(uint32_t*)&OT[w * 32 + g][c]      = pkbf(O0[cb][0] * i00, O0[cb][1] * i00);
        *(uint32_t*)&OT[w * 32 + g + 8][c]  = pkbf(O0[cb][2] * i01, O0[cb][3] * i01);
        *(uint32_t*)&OT[w * 32 + 16 + g][c] = pkbf(O1[cb][0] * i10, O1[cb][1] * i10);
        *(uint32_t*)&OT[w * 32 + 24 + g][c] = pkbf(O1[cb][2] * i11, O1[cb][3] * i11);
    }
    __syncthreads();
    __nv_bfloat16* Og = o + (size_t)(nb * CC + h * HD) * L;
    for (int u = t; u < 4096; u += 128) {
        int c = u >> 6, ip = u & 63;           // 64 channels x 64 bf162-pairs
        __nv_bfloat162 h2;
        h2.x = OT[2 * ip][c];
        h2.y = OT[2 * ip + 1][c];
        *(uint32_t*)&Og[(size_t)c * L + i0 + 2 * ip] = *(uint32_t*)&h2;
    }
}

// ---------------- launch -----------------------------------------------------
extern "C" void kernel_launch(void* const* d_in, const int* in_sizes, int n_in,
                              void* d_out, int out_size) {
    const float* x    = (const float*)d_in[0];
    const int*   mask = (const int*)  d_in[1];
    const float* nw   = (const float*)d_in[2];
    const float* nbb  = (const float*)d_in[3];
    const float* qw   = (const float*)d_in[4];
    const float* qb   = (const float*)d_in[5];
    const float* kw   = (const float*)d_in[6];
    const float* kb   = (const float*)d_in[7];
    const float* vw   = (const float*)d_in[8];
    const float* vb   = (const float*)d_in[9];
    const float* pw   = (const float*)d_in[10];
    const float* pb   = (const float*)d_in[11];
    float* out = (float*)d_out;

    float* part;
    __nv_bfloat16 *qt, *kt, *xnb, *ob, *wq, *wk, *wv, *wp;
    __half* vt;
    cudaGetSymbolAddress((void**)&part, g_part);
    cudaGetSymbolAddress((void**)&qt,   g_qt);
    cudaGetSymbolAddress((void**)&kt,   g_kt);
    cudaGetSymbolAddress((void**)&vt,   g_vt);
    cudaGetSymbolAddress((void**)&xnb,  g_xnb);
    cudaGetSymbolAddress((void**)&ob,   g_ob);
    cudaGetSymbolAddress((void**)&wq,   g_wq);
    cudaGetSymbolAddress((void**)&wk,   g_wk);
    cudaGetSymbolAddress((void**)&wv,   g_wv);
    cudaGetSymbolAddress((void**)&wp,   g_wp);

    static int inited = 0;
    if (!inited) {
        cudaFuncSetAttribute(flash_kernel,
                             cudaFuncAttributeMaxDynamicSharedMemorySize, FLASH_SMEM);
        inited = 1;
    }

    prep_kernel<<<416, 256>>>(x, qw, kw, vw, pw, mask, part, wq, wk, wv, wp,
                              out + (size_t)NB * CC * L);
    gn_apply_kernel<<<256, 256>>>(x, part, nw, nbb, xnb);

    qkv_kernel<<<dim3(32, 4, 6), 256>>>(xnb, wq, wk, wv, qb, kb, vb, qt, kt, vt);

    flash_kernel<<<dim3(32, 8), 128, FLASH_SMEM>>>(qt, kt, vt, ob);

    proj_kernel<<<dim3(32, 4, 2), 256>>>(ob, wp, pb, x, out);
}

// round 12
// speedup vs baseline: 1.0451x; 1.0451x over previous
#include <cuda_runtime.h>
#include <cuda_bf16.h>
#include <cuda_fp16.h>
#include <cstdint>

#define L 4096
#define CC 256
#define NB 2
#define NH 4
#define HD 64

// ---------------- mma / ldmatrix / cp.async helpers -------------------------
__device__ __forceinline__ void mma_bf16(float* d,
                                         uint32_t a0, uint32_t a1, uint32_t a2, uint32_t a3,
                                         uint32_t b0, uint32_t b1) {
    asm volatile(
        "mma.sync.aligned.m16n8k16.row.col.f32.bf16.bf16.f32 "
        "{%0,%1,%2,%3}, {%4,%5,%6,%7}, {%8,%9}, {%0,%1,%2,%3};"
        : "+f"(d[0]), "+f"(d[1]), "+f"(d[2]), "+f"(d[3])
        : "r"(a0), "r"(a1), "r"(a2), "r"(a3), "r"(b0), "r"(b1));
}
__device__ __forceinline__ void mma_f16(float* d,
                                        uint32_t a0, uint32_t a1, uint32_t a2, uint32_t a3,
                                        uint32_t b0, uint32_t b1) {
    asm volatile(
        "mma.sync.aligned.m16n8k16.row.col.f32.f16.f16.f32 "
        "{%0,%1,%2,%3}, {%4,%5,%6,%7}, {%8,%9}, {%0,%1,%2,%3};"
        : "+f"(d[0]), "+f"(d[1]), "+f"(d[2]), "+f"(d[3])
        : "r"(a0), "r"(a1), "r"(a2), "r"(a3), "r"(b0), "r"(b1));
}
// f16-accumulator variant: D/C are 2 f16x2 regs (row g, row g+8)
__device__ __forceinline__ void mma_f16h(uint32_t* d,
                                         uint32_t a0, uint32_t a1, uint32_t a2, uint32_t a3,
                                         uint32_t b0, uint32_t b1) {
    asm volatile(
        "mma.sync.aligned.m16n8k16.row.col.f16.f16.f16.f16 "
        "{%0,%1}, {%2,%3,%4,%5}, {%6,%7}, {%0,%1};"
        : "+r"(d[0]), "+r"(d[1])
        : "r"(a0), "r"(a1), "r"(a2), "r"(a3), "r"(b0), "r"(b1));
}
__device__ __forceinline__ uint32_t pkbf(float lo, float hi) {
    __nv_bfloat162 h = __floats2bfloat162_rn(lo, hi);
    return *(uint32_t*)&h;
}
__device__ __forceinline__ uint32_t pkhf(float lo, float hi) {
    __half2 h = __floats2half2_rn(lo, hi);
    return *(uint32_t*)&h;
}
__device__ __forceinline__ uint32_t ex2h2(uint32_t v) {
    uint32_t r;
    asm("ex2.approx.f16x2 %0, %1;" : "=r"(r) : "r"(v));
    return r;
}
__device__ __forceinline__ uint32_t hadd2u(uint32_t a, uint32_t b) {
    uint32_t d;
    asm("add.f16x2 %0, %1, %2;" : "=r"(d) : "r"(a), "r"(b));
    return d;
}
__device__ __forceinline__ float h2sum(uint32_t v) {
    __half2 h = *(__half2*)&v;
    float2 f = __half22float2(h);
    return f.x + f.y;
}
__device__ __forceinline__ uint32_t smem_u32(const void* p) {
    return (uint32_t)__cvta_generic_to_shared(p);
}
__device__ __forceinline__ void ldm_x4(uint32_t* r, uint32_t a) {
    asm volatile("ldmatrix.sync.aligned.m8n8.x4.shared.b16 {%0,%1,%2,%3}, [%4];"
        : "=r"(r[0]), "=r"(r[1]), "=r"(r[2]), "=r"(r[3]) : "r"(a));
}
__device__ __forceinline__ void ldm_x4t(uint32_t* r, uint32_t a) {
    asm volatile("ldmatrix.sync.aligned.m8n8.x4.trans.shared.b16 {%0,%1,%2,%3}, [%4];"
        : "=r"(r[0]), "=r"(r[1]), "=r"(r[2]), "=r"(r[3]) : "r"(a));
}
#define CPA16(dst, src) \
    asm volatile("cp.async.cg.shared.global [%0], [%1], 16;" :: "r"(dst), "l"(src) : "memory")
#define CPA_COMMIT() asm volatile("cp.async.commit_group;" ::: "memory")
#define CPA_WAIT1()  asm volatile("cp.async.wait_group 1;" ::: "memory")
#define CPA_WAIT0()  asm volatile("cp.async.wait_group 0;" ::: "memory")

// ---------------- scratch ----------------------------------------------------
__device__ __half        g_qt[(size_t)NB * NH * L * HD];   // [nh][i][d] f16 (pre-scaled log2e/8)
__device__ __half        g_kt[(size_t)NB * NH * L * HD];   // [nh][j][d] f16
__device__ __half        g_vt[(size_t)NB * CC * L];        // [nb][ch][j] f16
__device__ __nv_bfloat16 g_xnb[(size_t)NB * CC * L];
__device__ __nv_bfloat16 g_ob[(size_t)NB * CC * L];
__device__ __nv_bfloat16 g_wq[CC * CC], g_wk[CC * CC], g_wv[CC * CC], g_wp[CC * CC];
__device__ float         g_part[16 * 8 * 2];

#define QSCALE 0.18033688011112042f   // 0.125 * log2(e)

// ---------------- prep: wcvt + gn_part + mask fused --------------------------
__global__ void prep_kernel(const float* __restrict__ x,
                            const float* __restrict__ qw, const float* __restrict__ kw,
                            const float* __restrict__ vw, const float* __restrict__ pw,
                            const int* __restrict__ mask,
                            float* __restrict__ part,
                            __nv_bfloat16* __restrict__ wq, __nv_bfloat16* __restrict__ wk,
                            __nv_bfloat16* __restrict__ wv, __nv_bfloat16* __restrict__ wp,
                            float* __restrict__ mout) {
    int b = blockIdx.x;
    if (b < 128) {
        int ng = b >> 3, sl = b & 7;
        const float4* xp = (const float4*)(x + ((size_t)ng * 32) * L + (size_t)sl * 16384);
        float s = 0.f, s2 = 0.f;
        for (int i = threadIdx.x; i < 4096; i += 256) {
            float4 v = xp[i];
            s += v.x + v.y + v.z + v.w;
            s2 += v.x * v.x + v.y * v.y + v.z * v.z + v.w * v.w;
        }
        __shared__ float sh1[256], sh2[256];
        sh1[threadIdx.x] = s; sh2[threadIdx.x] = s2;
        __syncthreads();
        for (int st = 128; st > 0; st >>= 1) {
            if (threadIdx.x < st) {
                sh1[threadIdx.x] += sh1[threadIdx.x + st];
                sh2[threadIdx.x] += sh2[threadIdx.x + st];
            }
            __syncthreads();
        }
        if (threadIdx.x == 0) {
            part[(ng * 8 + sl) * 2 + 0] = sh1[0];
            part[(ng * 8 + sl) * 2 + 1] = sh2[0];
        }
    } else if (b < 384) {
        int i = (b - 128) * 256 + threadIdx.x;
        wq[i] = __float2bfloat16(qw[i] * QSCALE);
        wk[i] = __float2bfloat16(kw[i]);
        wv[i] = __float2bfloat16(vw[i]);
        wp[i] = __float2bfloat16(pw[i]);
    } else {
        int i = (b - 384) * 256 + threadIdx.x;
        if (i < NB * L) mout[i] = (float)mask[i];
    }
}

__global__ void gn_apply_kernel(const float* __restrict__ x,
                                const float* __restrict__ part,
                                const float* __restrict__ w,
                                const float* __restrict__ b,
                                __nv_bfloat16* __restrict__ xnb) {
    size_t base = (size_t)blockIdx.x * 8192;
    int ng = (int)(base >> 17);
    float s = 0.f, s2 = 0.f;
#pragma unroll
    for (int sl = 0; sl < 8; sl++) {
        s  += part[(ng * 8 + sl) * 2 + 0];
        s2 += part[(ng * 8 + sl) * 2 + 1];
    }
    float mean = s / 131072.f;
    float var = s2 / 131072.f - mean * mean;
    float rstd = rsqrtf(var + 1e-5f);
    const float4* xp = (const float4*)(x + base);
    for (int i = threadIdx.x; i < 2048; i += 256) {
        size_t idx = base + (size_t)i * 4;
        int c = (int)((idx >> 12) & 255);
        float sc = rstd * w[c], of = b[c] - mean * sc;
        float4 v = xp[i];
        __nv_bfloat162 lo = __floats2bfloat162_rn(v.x * sc + of, v.y * sc + of);
        __nv_bfloat162 hi = __floats2bfloat162_rn(v.z * sc + of, v.w * sc + of);
        uint2 pk = make_uint2(*(uint32_t*)&lo, *(uint32_t*)&hi);
        *(uint2*)&xnb[idx] = pk;
    }
}

// ---------------- conv core: 64m x 128n tile, k=256, triple-buffered --------
#define CONV_SMEM 41472
__device__ __forceinline__ __nv_bfloat16 (*WsB(char* csm, int buf))[40] {
    return (__nv_bfloat16(*)[40])(csm + buf * 5120);
}
__device__ __forceinline__ __nv_bfloat16 (*XsB(char* csm, int buf))[136] {
    return (__nv_bfloat16(*)[136])(csm + 15360 + buf * 8704);
}

__device__ __forceinline__
void conv_stage(char* csm, int buf, const __nv_bfloat16* W, const __nv_bfloat16* X,
                int m0, int n0, int k0, int t) {
    {
        int row = t >> 2, seg = t & 3;
        CPA16(smem_u32(&WsB(csm, buf)[row][seg * 8]),
              W + (size_t)(m0 + row) * CC + k0 + seg * 8);
    }
#pragma unroll
    for (int rep = 0; rep < 2; rep++) {
        int idx = t + rep * 256;
        int row = idx >> 4, seg = idx & 15;
        CPA16(smem_u32(&XsB(csm, buf)[row][seg * 8]),
              X + (size_t)(k0 + row) * L + n0 + seg * 8);
    }
    CPA_COMMIT();
}

// warp layout: 4 m-warps x 2 n-warps; per-warp 16m x 64n
__device__ __forceinline__
void conv_core(char* csm, const __nv_bfloat16* W, const __nv_bfloat16* X,
               int m0, int n0, float acc[8][4]) {
    const int t = threadIdx.x, lane = t & 31, w = t >> 5;
    const int mw = (w >> 1) * 16, nb0 = (w & 1) * 64;
    const int l16 = lane & 15, lh = lane >> 4;
    conv_stage(csm, 0, W, X, m0, n0, 0, t);
    conv_stage(csm, 1, W, X, m0, n0, 32, t);
    for (int i = 0; i < 8; i++) {
        if (i < 7) CPA_WAIT1(); else CPA_WAIT0();
        __syncthreads();
        if (i + 2 < 8) conv_stage(csm, (i + 2) % 3, W, X, m0, n0, (i + 2) * 32, t);
        __nv_bfloat16 (*Ws)[40]  = WsB(csm, i % 3);
        __nv_bfloat16 (*Xs)[136] = XsB(csm, i % 3);
#pragma unroll
        for (int kd = 0; kd < 2; kd++) {
            uint32_t a[4];
            ldm_x4(a, smem_u32(&Ws[mw + l16][kd * 16 + lh * 8]));
#pragma unroll
            for (int nbp = 0; nbp < 4; nbp++) {
                uint32_t b[4];
                ldm_x4t(b, smem_u32(&Xs[kd * 16 + l16][nb0 + nbp * 16 + lh * 8]));
                mma_bf16(acc[2 * nbp],     a[0], a[1], a[2], a[3], b[0], b[1]);
                mma_bf16(acc[2 * nbp + 1], a[0], a[1], a[2], a[3], b[2], b[3]);
            }
        }
    }
}

// fused q/k/v conv: z = type*2 + batch ; each block does TWO 128-n halves
__global__ __launch_bounds__(256, 3)
void qkv_kernel(const __nv_bfloat16* __restrict__ xnb,
                const __nv_bfloat16* __restrict__ wq, const __nv_bfloat16* __restrict__ wk,
                const __nv_bfloat16* __restrict__ wv,
                const float* __restrict__ qbias, const float* __restrict__ kbias,
                const float* __restrict__ vbias,
                __half* __restrict__ qt, __half* __restrict__ kt,
                __half* __restrict__ vt) {
    __shared__ __align__(16) char csm[CONV_SMEM];
    const int type = blockIdx.z >> 1, nbatch = blockIdx.z & 1;
    const __nv_bfloat16* W = type == 0 ? wq : type == 1 ? wk : wv;
    const float* Bias = type == 0 ? qbias : type == 1 ? kbias : vbias;
    const float osc = type == 0 ? QSCALE : 1.0f;
    const __nv_bfloat16* X = xnb + (size_t)nbatch * CC * L;
    const int m0 = blockIdx.y * 64;
    const int t = threadIdx.x, lane = t & 31, w = t >> 5;
    const int g = lane >> 2, t4 = lane & 3;
    const int mw = (w >> 1) * 16, nb0 = (w & 1) * 64;

    float b0v = Bias[m0 + mw + g] * osc, b1v = Bias[m0 + mw + g + 8] * osc;

    for (int half = 0; half < 2; half++) {
        const int n0 = blockIdx.x * 256 + half * 128;
        float acc[8][4];
#pragma unroll
        for (int a = 0; a < 8; a++)
#pragma unroll
            for (int p = 0; p < 4; p++) acc[a][p] = 0.f;
        conv_core(csm, W, X, m0, n0, acc);

        if (type < 2) {
            // transpose epilogue into [nh][pos][d] as f16; head = blockIdx.y
            __syncthreads();
            __half (*T)[72] = (__half(*)[72])csm;   // [128 n][64 d]
#pragma unroll
            for (int f = 0; f < 8; f++) {
                int n = nb0 + 16 * (f >> 1) + 8 * (f & 1) + 2 * t4;
                T[n][mw + g]         = __float2half(acc[f][0] + b0v);
                T[n + 1][mw + g]     = __float2half(acc[f][1] + b0v);
                T[n][mw + g + 8]     = __float2half(acc[f][2] + b1v);
                T[n + 1][mw + g + 8] = __float2half(acc[f][3] + b1v);
            }
            __syncthreads();
            __half* Out = (type == 0 ? qt : kt) +
                ((size_t)(nbatch * 4 + blockIdx.y) * L + n0) * HD;
            for (int u = t; u < 4096; u += 256) {
                int n = u >> 5, dp = u & 31;
                *(uint32_t*)(Out + (size_t)n * HD + 2 * dp) = *(uint32_t*)&T[n][2 * dp];
            }
        } else {
            int mA = m0 + mw + g, mB = mA + 8;
#pragma unroll
            for (int f = 0; f < 8; f++) {
                int n = n0 + nb0 + 16 * (f >> 1) + 8 * (f & 1) + 2 * t4;
                *(uint32_t*)&vt[((size_t)nbatch * CC + mA) * L + n] = pkhf(acc[f][0] + b0v, acc[f][1] + b0v);
                *(uint32_t*)&vt[((size_t)nbatch * CC + mB) * L + n] = pkhf(acc[f][2] + b1v, acc[f][3] + b1v);
            }
        }
        __syncthreads();   // smem reuse safety before next half's staging
    }
}

// proj conv -> fp32 + residual
__global__ __launch_bounds__(256, 3)
void proj_kernel(const __nv_bfloat16* __restrict__ ob, const __nv_bfloat16* __restrict__ wp,
                 const float* __restrict__ pbias, const float* __restrict__ x,
                 float* __restrict__ out) {
    __shared__ __align__(16) char csm[CONV_SMEM];
    const int nbatch = blockIdx.z;
    const size_t off = (size_t)nbatch * CC * L;
    const int n0 = blockIdx.x * 128, m0 = blockIdx.y * 64;
    const int t = threadIdx.x, lane = t & 31, w = t >> 5;
    const int g = lane >> 2, t4 = lane & 3;
    const int mw = (w >> 1) * 16, nb0 = (w & 1) * 64;

    float acc[8][4];
#pragma unroll
    for (int a = 0; a < 8; a++)
#pragma unroll
        for (int p = 0; p < 4; p++) acc[a][p] = 0.f;
    conv_core(csm, wp, ob + off, m0, n0, acc);

    float b0v = pbias[m0 + mw + g], b1v = pbias[m0 + mw + g + 8];
    int mA = m0 + mw + g, mB = mA + 8;
#pragma unroll
    for (int f = 0; f < 8; f++) {
        int n = n0 + nb0 + 16 * (f >> 1) + 8 * (f & 1) + 2 * t4;
        float2 rA = *(const float2*)&x[off + (size_t)mA * L + n];
        float2 rB = *(const float2*)&x[off + (size_t)mB * L + n];
        *(float2*)&out[off + (size_t)mA * L + n] =
            make_float2(acc[f][0] + b0v + rA.x, acc[f][1] + b0v + rA.y);
        *(float2*)&out[off + (size_t)mB * L + n] =
            make_float2(acc[f][2] + b1v + rB.x, acc[f][3] + b1v + rB.y);
    }
}

// ---------------- flash attention: f16 S-accumulators -----------------------
// 128-thr CTAs, 2 CTAs/SM; 4 warps x 32 i-rows; j-tile 64; triple-buffered.
// S mma uses f16 D whose layout IS the PV A-fragment layout: ex2 in place.
#define FLASH_SMEM 55296
__global__ __launch_bounds__(128, 2)
void flash_kernel(const __half* __restrict__ qt,
                  const __half* __restrict__ kt,
                  const __half* __restrict__ vt,
                  __nv_bfloat16* __restrict__ o) {
    extern __shared__ __align__(16) char fsm[];
    const int t = threadIdx.x, lane = t & 31, w = t >> 5;   // w in 0..3
    const int g = lane >> 2, t4 = lane & 3;
    const int lrow = (lane & 7) + ((lane >> 4) << 3);
    const int lcol = ((lane >> 3) & 1) * 8;
    const int nh = blockIdx.y;
    const int nb = nh >> 2, h = nh & 3;
    const int i0 = blockIdx.x * 128, iw = i0 + w * 32;

    // two A-fragment sets: rows iw..iw+15 and iw+16..iw+31
    const __half* Qb0 = qt + ((size_t)nh * L + iw) * HD;
    const __half* Qb1 = Qb0 + (size_t)16 * HD;
    uint32_t qa0[4][4], qa1[4][4];
#pragma unroll
    for (int kd = 0; kd < 4; kd++) {
        qa0[kd][0] = *(const uint32_t*)(Qb0 + (size_t)g * HD + 16 * kd + 2 * t4);
        qa0[kd][1] = *(const uint32_t*)(Qb0 + (size_t)(g + 8) * HD + 16 * kd + 2 * t4);
        qa0[kd][2] = *(const uint32_t*)(Qb0 + (size_t)g * HD + 16 * kd + 8 + 2 * t4);
        qa0[kd][3] = *(const uint32_t*)(Qb0 + (size_t)(g + 8) * HD + 16 * kd + 8 + 2 * t4);
        qa1[kd][0] = *(const uint32_t*)(Qb1 + (size_t)g * HD + 16 * kd + 2 * t4);
        qa1[kd][1] = *(const uint32_t*)(Qb1 + (size_t)(g + 8) * HD + 16 * kd + 2 * t4);
        qa1[kd][2] = *(const uint32_t*)(Qb1 + (size_t)g * HD + 16 * kd + 8 + 2 * t4);
        qa1[kd][3] = *(const uint32_t*)(Qb1 + (size_t)(g + 8) * HD + 16 * kd + 8 + 2 * t4);
    }

    float O0[8][4], O1[8][4];
#pragma unroll
    for (int a = 0; a < 8; a++)
#pragma unroll
        for (int p = 0; p < 4; p++) { O0[a][p] = 0.f; O1[a][p] = 0.f; }
    float lr0 = 0.f, lr8 = 0.f, lr16 = 0.f, lr24 = 0.f;

    const __half* Kg = kt + (size_t)nh * L * HD;
    const __half* Vg = vt + (size_t)(nb * CC + h * HD) * L;

    auto stage = [&](int buf, int j0) {
        __half (*Kt_)[72] = (__half(*)[72])(fsm + buf * 9216);
        __half (*Vs_)[72] = (__half(*)[72])(fsm + 27648 + buf * 9216);
#pragma unroll
        for (int rep = 0; rep < 4; rep++) {
            int idx = t + rep * 128;
            int r = idx >> 3, seg = idx & 7;
            CPA16(smem_u32(&Kt_[r][seg * 8]), Kg + (size_t)(j0 + r) * HD + seg * 8);
            CPA16(smem_u32(&Vs_[r][seg * 8]), Vg + (size_t)r * L + j0 + seg * 8);
        }
        CPA_COMMIT();
    };

    stage(0, 0);
    stage(1, 64);
    __syncthreads();

    for (int jt = 0; jt < 64; jt++) {
        if (jt < 63) CPA_WAIT1(); else CPA_WAIT0();
        __syncthreads();
        if (jt < 62) stage((jt + 2) % 3, (jt + 2) * 64);
        __half (*Kt_)[72] = (__half(*)[72])(fsm + (jt % 3) * 9216);
        __half (*Vs_)[72] = (__half(*)[72])(fsm + 27648 + (jt % 3) * 9216);

        // S = Q K^T with f16 accumulators: S0h[sb] = {row g pair, row g+8 pair}
        uint32_t S0h[8][2], S1h[8][2];
#pragma unroll
        for (int a = 0; a < 8; a++) {
            S0h[a][0] = 0u; S0h[a][1] = 0u;
            S1h[a][0] = 0u; S1h[a][1] = 0u;
        }
#pragma unroll
        for (int kd = 0; kd < 4; kd++) {
#pragma unroll
            for (int sbp = 0; sbp < 4; sbp++) {
                uint32_t b[4];
                ldm_x4(b, smem_u32(&Kt_[16 * sbp + lrow][16 * kd + lcol]));
                mma_f16h(S0h[2 * sbp],     qa0[kd][0], qa0[kd][1], qa0[kd][2], qa0[kd][3], b[0], b[1]);
                mma_f16h(S0h[2 * sbp + 1], qa0[kd][0], qa0[kd][1], qa0[kd][2], qa0[kd][3], b[2], b[3]);
                mma_f16h(S1h[2 * sbp],     qa1[kd][0], qa1[kd][1], qa1[kd][2], qa1[kd][3], b[0], b[1]);
                mma_f16h(S1h[2 * sbp + 1], qa1[kd][0], qa1[kd][1], qa1[kd][2], qa1[kd][3], b[2], b[3]);
            }
        }

        // ex2 in place -> P frags already in A-layout; O += P V^T; HADD2 sums
        uint32_t h0 = 0, h8 = 0, h16 = 0, h24 = 0;
#pragma unroll
        for (int kk = 0; kk < 4; kk++) {
            uint32_t pa0 = ex2h2(S0h[2 * kk][0]);       // row g,   j 16kk+2t4..
            uint32_t pa1 = ex2h2(S0h[2 * kk][1]);       // row g+8
            uint32_t pa2 = ex2h2(S0h[2 * kk + 1][0]);   // row g,   j +8
            uint32_t pa3 = ex2h2(S0h[2 * kk + 1][1]);   // row g+8, j +8
            uint32_t pb0 = ex2h2(S1h[2 * kk][0]);
            uint32_t pb1 = ex2h2(S1h[2 * kk][1]);
            uint32_t pb2 = ex2h2(S1h[2 * kk + 1][0]);
            uint32_t pb3 = ex2h2(S1h[2 * kk + 1][1]);
            h0  = hadd2u(h0,  hadd2u(pa0, pa2));
            h8  = hadd2u(h8,  hadd2u(pa1, pa3));
            h16 = hadd2u(h16, hadd2u(pb0, pb2));
            h24 = hadd2u(h24, hadd2u(pb1, pb3));
#pragma unroll
            for (int cbp = 0; cbp < 4; cbp++) {
                uint32_t b[4];
                ldm_x4(b, smem_u32(&Vs_[16 * cbp + lrow][16 * kk + lcol]));
                mma_f16(O0[2 * cbp],     pa0, pa1, pa2, pa3, b[0], b[1]);
                mma_f16(O0[2 * cbp + 1], pa0, pa1, pa2, pa3, b[2], b[3]);
                mma_f16(O1[2 * cbp],     pb0, pb1, pb2, pb3, b[0], b[1]);
                mma_f16(O1[2 * cbp + 1], pb0, pb1, pb2, pb3, b[2], b[3]);
            }
        }
        lr0  += h2sum(h0);
        lr8  += h2sum(h8);
        lr16 += h2sum(h16);
        lr24 += h2sum(h24);
    }

    // complete row sums across the lane quad (t4 dimension = columns)
    lr0  += __shfl_xor_sync(0xffffffffu, lr0, 1);
    lr0  += __shfl_xor_sync(0xffffffffu, lr0, 2);
    lr8  += __shfl_xor_sync(0xffffffffu, lr8, 1);
    lr8  += __shfl_xor_sync(0xffffffffu, lr8, 2);
    lr16 += __shfl_xor_sync(0xffffffffu, lr16, 1);
    lr16 += __shfl_xor_sync(0xffffffffu, lr16, 2);
    lr24 += __shfl_xor_sync(0xffffffffu, lr24, 1);
    lr24 += __shfl_xor_sync(0xffffffffu, lr24, 2);
    float i00 = 1.f / lr0, i01 = 1.f / lr8, i10 = 1.f / lr16, i11 = 1.f / lr24;

    __syncthreads();
    __nv_bfloat16 (*OT)[72] = (__nv_bfloat16(*)[72])fsm;   // [128 i][64 c]
#pragma unroll
    for (int cb = 0; cb < 8; cb++) {
        int c = 8 * cb + 2 * t4;
        *(uint32_t*)&OT[w * 32 + g][c]      = pkbf(O0[cb][0] * i00, O0[cb][1] * i00);
        *(uint32_t*)&OT[w * 32 + g + 8][c]  = pkbf(O0[cb][2] * i01, O0[cb][3] * i01);
        *(uint32_t*)&OT[w * 32 + 16 + g][c] = pkbf(O1[cb][0] * i10, O1[cb][1] * i10);
        *(uint32_t*)&OT[w * 32 + 24 + g][c] = pkbf(O1[cb][2] * i11, O1[cb][3] * i11);
    }
    __syncthreads();
    __nv_bfloat16* Og = o + (size_t)(nb * CC + h * HD) * L;
    for (int u = t; u < 4096; u += 128) {
        int c = u >> 6, ip = u & 63;
        __nv_bfloat162 h2;
        h2.x = OT[2 * ip][c];
        h2.y = OT[2 * ip + 1][c];
        *(uint32_t*)&Og[(size_t)c * L + i0 + 2 * ip] = *(uint32_t*)&h2;
    }
}

// ---------------- launch -----------------------------------------------------
extern "C" void kernel_launch(void* const* d_in, const int* in_sizes, int n_in,
                              void* d_out, int out_size) {
    const float* x    = (const float*)d_in[0];
    const int*   mask = (const int*)  d_in[1];
    const float* nw   = (const float*)d_in[2];
    const float* nbb  = (const float*)d_in[3];
    const float* qw   = (const float*)d_in[4];
    const float* qb   = (const float*)d_in[5];
    const float* kw   = (const float*)d_in[6];
    const float* kb   = (const float*)d_in[7];
    const float* vw   = (const float*)d_in[8];
    const float* vb   = (const float*)d_in[9];
    const float* pw   = (const float*)d_in[10];
    const float* pb   = (const float*)d_in[11];
    float* out = (float*)d_out;

    float* part;
    __nv_bfloat16 *xnb, *ob, *wq, *wk, *wv, *wp;
    __half *qt, *kt, *vt;
    cudaGetSymbolAddress((void**)&part, g_part);
    cudaGetSymbolAddress((void**)&qt,   g_qt);
    cudaGetSymbolAddress((void**)&kt,   g_kt);
    cudaGetSymbolAddress((void**)&vt,   g_vt);
    cudaGetSymbolAddress((void**)&xnb,  g_xnb);
    cudaGetSymbolAddress((void**)&ob,   g_ob);
    cudaGetSymbolAddress((void**)&wq,   g_wq);
    cudaGetSymbolAddress((void**)&wk,   g_wk);
    cudaGetSymbolAddress((void**)&wv,   g_wv);
    cudaGetSymbolAddress((void**)&wp,   g_wp);

    static int inited = 0;
    if (!inited) {
        cudaFuncSetAttribute(flash_kernel,
                             cudaFuncAttributeMaxDynamicSharedMemorySize, FLASH_SMEM);
        inited = 1;
    }

    prep_kernel<<<416, 256>>>(x, qw, kw, vw, pw, mask, part, wq, wk, wv, wp,
                              out + (size_t)NB * CC * L);
    gn_apply_kernel<<<256, 256>>>(x, part, nw, nbb, xnb);

    qkv_kernel<<<dim3(16, 4, 6), 256>>>(xnb, wq, wk, wv, qb, kb, vb, qt, kt, vt);

    flash_kernel<<<dim3(32, 8), 128, FLASH_SMEM>>>(qt, kt, vt, ob);

    proj_kernel<<<dim3(32, 4, 2), 256>>>(ob, wp, pb, x, out);
}